// round 12
// baseline (speedup 1.0000x reference)
#include <cuda_runtime.h>

#define NS   128         // samples per ray
#define NH   64          // hidden units
#define RPB  4           // rays per block (one warp per ray)
#define THREADS 128

typedef unsigned long long u64;

__device__ __forceinline__ u64 ffma2(u64 a, u64 b, u64 c) {
    u64 d;
    asm("fma.rn.f32x2 %0, %1, %2, %3;" : "=l"(d) : "l"(a), "l"(b), "l"(c));
    return d;
}
__device__ __forceinline__ u64 pack2(float lo, float hi) {
    u64 r;
    asm("mov.b64 %0, {%1, %2};" : "=l"(r) : "f"(lo), "f"(hi));
    return r;
}
__device__ __forceinline__ u64 relu2(u64 x) {
    float lo, hi;
    asm("mov.b64 {%0, %1}, %2;" : "=f"(lo), "=f"(hi) : "l"(x));
    lo = fmaxf(lo, 0.0f);
    hi = fmaxf(hi, 0.0f);
    return pack2(lo, hi);
}
__device__ __forceinline__ float sum2(u64 x) {   // lo + hi
    float lo, hi;
    asm("mov.b64 {%0, %1}, %2;" : "=f"(lo), "=f"(hi) : "l"(x));
    return lo + hi;
}
__device__ __forceinline__ float tanh_fast(float x) {
    float y;
    asm("tanh.approx.f32 %0, %1;" : "=f"(y) : "f"(x));
    return y;
}
// sigmoid(x) = 0.5*tanh(0.5x) + 0.5
__device__ __forceinline__ float sigmoid_fast(float x) {
    return fmaf(0.5f, tanh_fast(0.5f * x), 0.5f);
}

union F4U { float4 f; u64 q[2]; };

// Ray-independent output weights, transposed: warp-uniform -> constant bank
// (uniform datapath: frees the smem crossbar + reduces FFMA2 RF-bank pressure).
struct CW {
    float4 ws[NH/4];   // w_sigma
    float4 u0[NH/4];   // W_color[:,0]
    float4 u1[NH/4];   // W_color[:,1]
    float4 u2[NH/4];   // W_color[:,2]
};
__constant__ CW cW;
__device__   CW gScratch;

__global__ void repack_kernel(const float* __restrict__ w_sigma,
                              const float* __restrict__ W_color) {
    const int t = threadIdx.x;
    if (t < NH) {
        ((float*)gScratch.ws)[t] = w_sigma[t];
        ((float*)gScratch.u0)[t] = W_color[t*3+0];
        ((float*)gScratch.u1)[t] = W_color[t*3+1];
        ((float*)gScratch.u2)[t] = W_color[t*3+2];
    }
}

__global__ __launch_bounds__(THREADS, 8)
void nerf_render_kernel(
    const float* __restrict__ rays_o, const float* __restrict__ rays_d,
    const float* __restrict__ W1, const float* __restrict__ W2,
    const float* __restrict__ b1,
    float* __restrict__ out_image, float* __restrict__ out_depth,
    float* __restrict__ out_weights, float* __restrict__ out_wsum,
    const int BN)
{
    __shared__ float4 sBase4[RPB][NH/4];    // per-ray: o·W1 + d·W2 + b1
    __shared__ float4 sSlope4[RPB][NH/4];   // per-ray: d·W1

    const int tid  = threadIdx.x;
    const int lane = tid & 31;
    const int wid  = tid >> 5;
    const int r    = blockIdx.x * RPB + wid;
    const bool active = (r < BN);

    // ---- per-ray data (all lanes of a warp share one ray) ----
    float ox=0.f, oy=0.f, oz=0.f, dx=1.f, dy=1.f, dz=1.f;
    if (active) {
        ox = rays_o[r*3+0]; oy = rays_o[r*3+1]; oz = rays_o[r*3+2];
        dx = rays_d[r*3+0]; dy = rays_d[r*3+1]; dz = rays_d[r*3+2];
    }

    // ---- per-ray base/slope per hidden unit (2 units per lane) ----
    {
        float* bp = (float*)sBase4[wid];
        float* sp = (float*)sSlope4[wid];
        #pragma unroll
        for (int j = lane; j < NH; j += 32) {
            const float a0 = W1[j], a1 = W1[NH+j], a2 = W1[2*NH+j];
            sp[j] = dx*a0 + dy*a1 + dz*a2;
            bp[j] = ox*a0 + oy*a1 + oz*a2
                  + b1[j] + dx*W2[j] + dy*W2[NH+j] + dz*W2[2*NH+j];
        }
    }
    __syncwarp();

    // ---- near/far via cube AABB (replicates reference exactly) ----
    float near_t, far_t;
    {
        const float ivx = 1.0f/(dx + 1e-15f);
        const float ivy = 1.0f/(dy + 1e-15f);
        const float ivz = 1.0f/(dz + 1e-15f);
        const float t1x = (-1.0f - ox)*ivx, t2x = (1.0f - ox)*ivx;
        const float t1y = (-1.0f - oy)*ivy, t2y = (1.0f - oy)*ivy;
        const float t1z = (-1.0f - oz)*ivz, t2z = (1.0f - oz)*ivz;
        near_t = fmaxf(fmaxf(fminf(t1x,t2x), fminf(t1y,t2y)), fminf(t1z,t2z));
        far_t  = fminf(fminf(fmaxf(t1x,t2x), fmaxf(t1y,t2y)), fmaxf(t1z,t2z));
        if (far_t < near_t) { near_t = 1e9f; far_t = 1e9f; }   // miss
        near_t = fmaxf(near_t, 0.05f);                          // MIN_NEAR
    }
    const float span  = far_t - near_t;
    const float delta = span * (1.0f/(NS-1));

    // ---- 4 contiguous samples per lane: s = 4*lane + k ----
    // Keep only the packed {z,z} live through the loop; zv recomputed later.
    u64 zz[4];
    #pragma unroll
    for (int k = 0; k < 4; ++k) {
        const float z = near_t + span * ((float)(4*lane + k) * (1.0f/(NS-1)));
        zz[k] = pack2(z, z);
    }

    // ---- MLP: pair-packed units, 4 units per iteration ----
    u64 as[4] = {0,0,0,0};     // sigma
    u64 ar[4] = {0,0,0,0};     // color r
    u64 ag[4] = {0,0,0,0};     // color g
    u64 ab[4] = {0,0,0,0};     // color b

    #pragma unroll 4
    for (int u = 0; u < NH/4; ++u) {
        F4U bs, sl, ws, q0, q1, q2;
        bs.f = sBase4[wid][u];
        sl.f = sSlope4[wid][u];
        ws.f = cW.ws[u];       // constant bank (uniform path)
        q0.f = cW.u0[u];
        q1.f = cW.u1[u];
        q2.f = cW.u2[u];
        #pragma unroll
        for (int h = 0; h < 2; ++h) {      // two unit-pairs per float4
            const u64 B = bs.q[h], S = sl.q[h];
            #pragma unroll
            for (int k = 0; k < 4; ++k) {
                const u64 hp = relu2(ffma2(zz[k], S, B));
                as[k] = ffma2(hp, ws.q[h], as[k]);
                ar[k] = ffma2(hp, q0.q[h], ar[k]);
                ag[k] = ffma2(hp, q1.q[h], ag[k]);
                ab[k] = ffma2(hp, q2.q[h], ab[k]);
            }
        }
    }

    // ---- activations + alpha per sample ----
    // softplus in log2 domain, branch-free and always FINITE:
    //   t = log2(1+e^s) = max(s,0)*log2e + log2(1 + e^(-|s|))
    //   alpha = 1 - exp2(-delta*t);  no 0*inf when delta==0 (miss rays).
    const float LOG2E = 1.4426950408889634f;
    float alpha[4], v[4], rr[4], rg[4], rb[4];
    #pragma unroll
    for (int k = 0; k < 4; ++k) {
        const float sacc = sum2(as[k]);
        const float en   = __expf(-fabsf(sacc));
        const float t    = fmaxf(sacc, 0.0f) * LOG2E + __log2f(1.0f + en);
        rr[k] = sigmoid_fast(sum2(ar[k]));
        rg[k] = sigmoid_fast(sum2(ag[k]));
        rb[k] = sigmoid_fast(sum2(ab[k]));
        alpha[k] = 1.0f - exp2f(-delta * t);
        v[k]     = (1.0f - alpha[k]) + 1e-15f;
    }

    // ---- exclusive multiplicative scan over 128 samples (warp-local) ----
    const float l0 = v[0];
    const float l1 = l0 * v[1];
    const float l2 = l1 * v[2];
    const float l3 = l2 * v[3];
    float p = l3;
    #pragma unroll
    for (int off = 1; off < 32; off <<= 1) {
        const float n = __shfl_up_sync(0xffffffffu, p, off);
        if (lane >= off) p *= n;
    }
    float excl = __shfl_up_sync(0xffffffffu, p, 1);
    if (lane == 0) excl = 1.0f;
    float wt[4];
    wt[0] = alpha[0] * excl;
    wt[1] = alpha[1] * (excl * l0);
    wt[2] = alpha[2] * (excl * l1);
    wt[3] = alpha[3] * (excl * l2);

    // ---- outputs ----
    if (active) {
        float4 wv = make_float4(wt[0], wt[1], wt[2], wt[3]);
        *(float4*)(out_weights + (size_t)r * NS + 4*lane) = wv;
    }

    float s0 = 0.f, s1 = 0.f, s2 = 0.f, s3 = 0.f, s4 = 0.f;
    #pragma unroll
    for (int k = 0; k < 4; ++k) {
        const float zk = near_t + span * ((float)(4*lane + k) * (1.0f/(NS-1)));
        s0 += wt[k];
        s1 += wt[k] * zk;
        s2 += wt[k] * rr[k];
        s3 += wt[k] * rg[k];
        s4 += wt[k] * rb[k];
    }
    #pragma unroll
    for (int off = 16; off; off >>= 1) {
        s0 += __shfl_xor_sync(0xffffffffu, s0, off);
        s1 += __shfl_xor_sync(0xffffffffu, s1, off);
        s2 += __shfl_xor_sync(0xffffffffu, s2, off);
        s3 += __shfl_xor_sync(0xffffffffu, s3, off);
        s4 += __shfl_xor_sync(0xffffffffu, s4, off);
    }
    if (active && lane == 0) {
        out_wsum[r]      = s0;
        out_depth[r]     = s1;
        out_image[r*3+0] = s2;
        out_image[r*3+1] = s3;
        out_image[r*3+2] = s4;
    }
}

extern "C" void kernel_launch(void* const* d_in, const int* in_sizes, int n_in,
                              void* d_out, int out_size) {
    const float* rays_o  = (const float*)d_in[0];
    const float* rays_d  = (const float*)d_in[1];
    const float* W1      = (const float*)d_in[2];
    const float* W2      = (const float*)d_in[3];
    const float* b1      = (const float*)d_in[4];
    const float* w_sigma = (const float*)d_in[5];
    const float* W_color = (const float*)d_in[6];

    const int BN = in_sizes[0] / 3;   // B*N rays

    float* out = (float*)d_out;
    // output layout: image [BN,3], depth [BN], weights [BN,NS], weights_sum [BN]
    float* out_image   = out;
    float* out_depth   = out + (size_t)BN * 3;
    float* out_weights = out + (size_t)BN * 4;
    float* out_wsum    = out + (size_t)BN * 4 + (size_t)BN * NS;

    // 1) repack output weights into transposed layout in __device__ scratch
    repack_kernel<<<1, 64>>>(w_sigma, W_color);

    // 2) copy scratch -> __constant__ (D2D, graph-capturable, no allocation)
    void* scratch_ptr = nullptr;
    cudaGetSymbolAddress(&scratch_ptr, gScratch);
    cudaMemcpyToSymbolAsync(cW, scratch_ptr, sizeof(CW), 0,
                            cudaMemcpyDeviceToDevice, 0);

    // 3) main kernel
    const int blocks = (BN + RPB - 1) / RPB;
    nerf_render_kernel<<<blocks, THREADS>>>(rays_o, rays_d, W1, W2, b1,
                                            out_image, out_depth,
                                            out_weights, out_wsum, BN);
}

// round 13
// speedup vs baseline: 1.0672x; 1.0672x over previous
#include <cuda_runtime.h>

#define NS   128         // samples per ray
#define NH   64          // hidden units
#define RPB  4           // rays per block (one warp per ray)
#define THREADS 128

typedef unsigned long long u64;

__device__ __forceinline__ u64 ffma2(u64 a, u64 b, u64 c) {
    u64 d;
    asm("fma.rn.f32x2 %0, %1, %2, %3;" : "=l"(d) : "l"(a), "l"(b), "l"(c));
    return d;
}
__device__ __forceinline__ u64 add2(u64 a, u64 b) {
    u64 d;
    asm("add.rn.f32x2 %0, %1, %2;" : "=l"(d) : "l"(a), "l"(b));
    return d;
}
__device__ __forceinline__ u64 pack2(float lo, float hi) {
    u64 r;
    asm("mov.b64 %0, {%1, %2};" : "=l"(r) : "f"(lo), "f"(hi));
    return r;
}
__device__ __forceinline__ u64 relu2(u64 x) {
    float lo, hi;
    asm("mov.b64 {%0, %1}, %2;" : "=f"(lo), "=f"(hi) : "l"(x));
    lo = fmaxf(lo, 0.0f);
    hi = fmaxf(hi, 0.0f);
    return pack2(lo, hi);
}
__device__ __forceinline__ float sum2(u64 x) {   // lo + hi
    float lo, hi;
    asm("mov.b64 {%0, %1}, %2;" : "=f"(lo), "=f"(hi) : "l"(x));
    return lo + hi;
}
__device__ __forceinline__ float tanh_fast(float x) {
    float y;
    asm("tanh.approx.f32 %0, %1;" : "=f"(y) : "f"(x));
    return y;
}
// sigmoid(x) = 0.5*tanh(0.5x) + 0.5
__device__ __forceinline__ float sigmoid_fast(float x) {
    return fmaf(0.5f, tanh_fast(0.5f * x), 0.5f);
}

union F4U { float4 f; u64 q[2]; };

// Ray-independent output weights, transposed: warp-uniform -> constant bank
// (uniform datapath: LDCU -> UR operands keeps accum FFMA2 at rt=2).
struct CW {
    float4 ws[NH/4];   // w_sigma
    float4 u0[NH/4];   // W_color[:,0]
    float4 u1[NH/4];   // W_color[:,1]
    float4 u2[NH/4];   // W_color[:,2]
};
__constant__ CW cW;
__device__   CW gScratch;

__global__ void repack_kernel(const float* __restrict__ w_sigma,
                              const float* __restrict__ W_color) {
    const int t = threadIdx.x;
    if (t < NH) {
        ((float*)gScratch.ws)[t] = w_sigma[t];
        ((float*)gScratch.u0)[t] = W_color[t*3+0];
        ((float*)gScratch.u1)[t] = W_color[t*3+1];
        ((float*)gScratch.u2)[t] = W_color[t*3+2];
    }
}

__global__ __launch_bounds__(THREADS, 8)
void nerf_render_kernel(
    const float* __restrict__ rays_o, const float* __restrict__ rays_d,
    const float* __restrict__ W1, const float* __restrict__ W2,
    const float* __restrict__ b1,
    float* __restrict__ out_image, float* __restrict__ out_depth,
    float* __restrict__ out_weights, float* __restrict__ out_wsum,
    const int BN)
{
    __shared__ float4 sBase4[RPB][NH/4];    // per-ray: o·W1 + d·W2 + b1
    __shared__ float4 sSlope4[RPB][NH/4];   // per-ray: d·W1
    __shared__ float4 sSdz4[RPB][NH/4];     // per-ray: (d·W1)*step_z

    const int tid  = threadIdx.x;
    const int lane = tid & 31;
    const int wid  = tid >> 5;
    const int r    = blockIdx.x * RPB + wid;
    const bool active = (r < BN);

    // ---- per-ray data (all lanes of a warp share one ray) ----
    float ox=0.f, oy=0.f, oz=0.f, dx=1.f, dy=1.f, dz=1.f;
    if (active) {
        ox = rays_o[r*3+0]; oy = rays_o[r*3+1]; oz = rays_o[r*3+2];
        dx = rays_d[r*3+0]; dy = rays_d[r*3+1]; dz = rays_d[r*3+2];
    }

    // ---- near/far via cube AABB (replicates reference exactly) ----
    float near_t, far_t;
    {
        const float ivx = 1.0f/(dx + 1e-15f);
        const float ivy = 1.0f/(dy + 1e-15f);
        const float ivz = 1.0f/(dz + 1e-15f);
        const float t1x = (-1.0f - ox)*ivx, t2x = (1.0f - ox)*ivx;
        const float t1y = (-1.0f - oy)*ivy, t2y = (1.0f - oy)*ivy;
        const float t1z = (-1.0f - oz)*ivz, t2z = (1.0f - oz)*ivz;
        near_t = fmaxf(fmaxf(fminf(t1x,t2x), fminf(t1y,t2y)), fminf(t1z,t2z));
        far_t  = fminf(fminf(fmaxf(t1x,t2x), fmaxf(t1y,t2y)), fmaxf(t1z,t2z));
        if (far_t < near_t) { near_t = 1e9f; far_t = 1e9f; }   // miss
        near_t = fmaxf(near_t, 0.05f);                          // MIN_NEAR
    }
    const float span  = far_t - near_t;
    const float delta = span * (1.0f/(NS-1));   // == step_z

    // ---- per-ray base/slope/slope-step per hidden unit ----
    {
        float* bp = (float*)sBase4[wid];
        float* sp = (float*)sSlope4[wid];
        float* qp = (float*)sSdz4[wid];
        #pragma unroll
        for (int j = lane; j < NH; j += 32) {
            const float a0 = W1[j], a1 = W1[NH+j], a2 = W1[2*NH+j];
            const float sl = dx*a0 + dy*a1 + dz*a2;
            sp[j] = sl;
            qp[j] = sl * delta;
            bp[j] = ox*a0 + oy*a1 + oz*a2
                  + b1[j] + dx*W2[j] + dy*W2[NH+j] + dz*W2[2*NH+j];
        }
    }
    __syncwarp();

    // ---- first sample of this lane: s0 = 4*lane ----
    const float z0 = near_t + span * ((float)(4*lane) * (1.0f/(NS-1)));
    const u64 zz0 = pack2(z0, z0);

    // ---- MLP: pair-packed units; pre-act stepped incrementally in z ----
    u64 as[4] = {0,0,0,0};     // sigma
    u64 ar[4] = {0,0,0,0};     // color r
    u64 ag[4] = {0,0,0,0};     // color g
    u64 ab[4] = {0,0,0,0};     // color b

    #pragma unroll 8
    for (int u = 0; u < NH/4; ++u) {
        F4U bs, sl, sq, ws, q0, q1, q2;
        bs.f = sBase4[wid][u];
        sl.f = sSlope4[wid][u];
        sq.f = sSdz4[wid][u];
        ws.f = cW.ws[u];       // constant bank (uniform path)
        q0.f = cW.u0[u];
        q1.f = cW.u1[u];
        q2.f = cW.u2[u];
        #pragma unroll
        for (int h = 0; h < 2; ++h) {      // two unit-pairs per float4
            const u64 B = bs.q[h], S = sl.q[h], DZ = sq.q[h];
            u64 pre = ffma2(zz0, S, B);    // sample 4*lane
            #pragma unroll
            for (int k = 0; k < 4; ++k) {
                const u64 hp = relu2(pre);
                as[k] = ffma2(hp, ws.q[h], as[k]);
                ar[k] = ffma2(hp, q0.q[h], ar[k]);
                ag[k] = ffma2(hp, q1.q[h], ag[k]);
                ab[k] = ffma2(hp, q2.q[h], ab[k]);
                if (k < 3) pre = add2(pre, DZ);
            }
        }
    }

    // ---- activations + alpha per sample ----
    // softplus in log2 domain, branch-free and always FINITE:
    //   t = log2(1+e^s) = max(s,0)*log2e + log2(1 + e^(-|s|))
    //   alpha = 1 - exp2(-delta*t);  no 0*inf when delta==0 (miss rays).
    const float LOG2E = 1.4426950408889634f;
    float alpha[4], v[4], rr[4], rg[4], rb[4];
    #pragma unroll
    for (int k = 0; k < 4; ++k) {
        const float sacc = sum2(as[k]);
        const float en   = __expf(-fabsf(sacc));
        const float t    = fmaxf(sacc, 0.0f) * LOG2E + __log2f(1.0f + en);
        rr[k] = sigmoid_fast(sum2(ar[k]));
        rg[k] = sigmoid_fast(sum2(ag[k]));
        rb[k] = sigmoid_fast(sum2(ab[k]));
        alpha[k] = 1.0f - exp2f(-delta * t);
        v[k]     = (1.0f - alpha[k]) + 1e-15f;
    }

    // ---- exclusive multiplicative scan over 128 samples (warp-local) ----
    const float l0 = v[0];
    const float l1 = l0 * v[1];
    const float l2 = l1 * v[2];
    const float l3 = l2 * v[3];
    float p = l3;
    #pragma unroll
    for (int off = 1; off < 32; off <<= 1) {
        const float n = __shfl_up_sync(0xffffffffu, p, off);
        if (lane >= off) p *= n;
    }
    float excl = __shfl_up_sync(0xffffffffu, p, 1);
    if (lane == 0) excl = 1.0f;
    float wt[4];
    wt[0] = alpha[0] * excl;
    wt[1] = alpha[1] * (excl * l0);
    wt[2] = alpha[2] * (excl * l1);
    wt[3] = alpha[3] * (excl * l2);

    // ---- outputs ----
    if (active) {
        float4 wv = make_float4(wt[0], wt[1], wt[2], wt[3]);
        *(float4*)(out_weights + (size_t)r * NS + 4*lane) = wv;
    }

    float s0 = 0.f, s1 = 0.f, s2 = 0.f, s3 = 0.f, s4 = 0.f;
    #pragma unroll
    for (int k = 0; k < 4; ++k) {
        const float zk = near_t + span * ((float)(4*lane + k) * (1.0f/(NS-1)));
        s0 += wt[k];
        s1 += wt[k] * zk;
        s2 += wt[k] * rr[k];
        s3 += wt[k] * rg[k];
        s4 += wt[k] * rb[k];
    }
    #pragma unroll
    for (int off = 16; off; off >>= 1) {
        s0 += __shfl_xor_sync(0xffffffffu, s0, off);
        s1 += __shfl_xor_sync(0xffffffffu, s1, off);
        s2 += __shfl_xor_sync(0xffffffffu, s2, off);
        s3 += __shfl_xor_sync(0xffffffffu, s3, off);
        s4 += __shfl_xor_sync(0xffffffffu, s4, off);
    }
    if (active && lane == 0) {
        out_wsum[r]      = s0;
        out_depth[r]     = s1;
        out_image[r*3+0] = s2;
        out_image[r*3+1] = s3;
        out_image[r*3+2] = s4;
    }
}

extern "C" void kernel_launch(void* const* d_in, const int* in_sizes, int n_in,
                              void* d_out, int out_size) {
    const float* rays_o  = (const float*)d_in[0];
    const float* rays_d  = (const float*)d_in[1];
    const float* W1      = (const float*)d_in[2];
    const float* W2      = (const float*)d_in[3];
    const float* b1      = (const float*)d_in[4];
    const float* w_sigma = (const float*)d_in[5];
    const float* W_color = (const float*)d_in[6];

    const int BN = in_sizes[0] / 3;   // B*N rays

    float* out = (float*)d_out;
    // output layout: image [BN,3], depth [BN], weights [BN,NS], weights_sum [BN]
    float* out_image   = out;
    float* out_depth   = out + (size_t)BN * 3;
    float* out_weights = out + (size_t)BN * 4;
    float* out_wsum    = out + (size_t)BN * 4 + (size_t)BN * NS;

    // 1) repack output weights into transposed layout in __device__ scratch
    repack_kernel<<<1, 64>>>(w_sigma, W_color);

    // 2) copy scratch -> __constant__ (D2D, graph-capturable, no allocation)
    void* scratch_ptr = nullptr;
    cudaGetSymbolAddress(&scratch_ptr, gScratch);
    cudaMemcpyToSymbolAsync(cW, scratch_ptr, sizeof(CW), 0,
                            cudaMemcpyDeviceToDevice, 0);

    // 3) main kernel
    const int blocks = (BN + RPB - 1) / RPB;
    nerf_render_kernel<<<blocks, THREADS>>>(rays_o, rays_d, W1, W2, b1,
                                            out_image, out_depth,
                                            out_weights, out_wsum, BN);
}